// round 5
// baseline (speedup 1.0000x reference)
#include <cuda_runtime.h>

// NCELoss: N=4096 examples, E=1024 embed, K=50 noise samples (+1 target).
// Inputs (metadata order):
//   d_in[0] input  f32 [N,E]
//   d_in[1] target i32 [N]
//   d_in[2] noise_samples i32 [N,K]
//   d_in[3] noise  f32 [V]
//   d_in[4] weight f32 [V,E]
//   d_in[5] bias   f32 [V]
// Output: scalar f32 loss.
//
// Two kernels, no atomics:
//   1) main: one block per example, 17 warps (544 thr) -> 51 columns split
//      exactly 3 per warp. Input row staged in smem. Plain __ldg float4
//      weight loads (8 in flight per warp). Writes g_partial[n].
//   2) finalize: one block reduces all N partials in double (fixed order)
//      and writes the scalar. No zeroing needed: every partial slot is
//      rewritten every call.

#define EDIM 1024
#define KNOISE 50
#define NORM_TERM 9.0f
#define NWARPS 17
#define MAXN 8192

__device__ double g_partial[MAXN];

__device__ __forceinline__ float loss_term(int j, int idx, float s,
                                           const float* __restrict__ bias,
                                           const float* __restrict__ noise)
{
    const float logit = s + __ldg(&bias[idx]);
    const float p  = expf(logit - NORM_TERM);
    const float kp = (float)KNOISE * __ldg(&noise[idx]);
    const float num = (j == 0) ? p : kp;   // j==0: data term, else noise term
    return logf(num / (p + kp));
}

__global__ __launch_bounds__(NWARPS * 32) void nce_loss_kernel(
    const float* __restrict__ input,
    const int*   __restrict__ target,
    const int*   __restrict__ noise_samples,
    const float* __restrict__ noise,
    const float* __restrict__ weight,
    const float* __restrict__ bias)
{
    __shared__ float4 s_in[EDIM / 4];      // 4 KB: this example's input row
    __shared__ float  s_wsum[NWARPS];

    const int n    = blockIdx.x;
    const int tid  = threadIdx.x;
    const int lane = tid & 31;
    const int wid  = tid >> 5;

    // Stage input row into smem (vectorized, coalesced).
    const float4* in4 = reinterpret_cast<const float4*>(input + (size_t)n * EDIM);
    for (int i = tid; i < EDIM / 4; i += NWARPS * 32) s_in[i] = in4[i];
    __syncthreads();

    // 51 columns, 17 warps -> exactly 3 columns per warp (perfect balance).
    float acc = 0.0f;
    #pragma unroll
    for (int t = 0; t < 3; t++) {
        const int j = wid + t * NWARPS;
        const int idx = (j == 0) ? __ldg(&target[n])
                                 : __ldg(&noise_samples[n * KNOISE + (j - 1)]);
        const float4* w4 = reinterpret_cast<const float4*>(weight + (size_t)idx * EDIM);

        // 1024-float dot: 8 x LDG.128 per lane, front-batched for MLP.
        float4 w[8];
        #pragma unroll
        for (int i = 0; i < 8; i++) w[i] = __ldg(&w4[lane + 32 * i]);

        float s = 0.0f;
        #pragma unroll
        for (int i = 0; i < 8; i++) {
            const float4 x = s_in[lane + 32 * i];
            s += w[i].x * x.x + w[i].y * x.y + w[i].z * x.z + w[i].w * x.w;
        }
        #pragma unroll
        for (int o = 16; o; o >>= 1) s += __shfl_xor_sync(0xffffffffu, s, o);

        if (lane == 0) acc += loss_term(j, idx, s, bias, noise);
    }

    if (lane == 0) s_wsum[wid] = acc;
    __syncthreads();

    if (wid == 0) {
        float v = (lane < NWARPS) ? s_wsum[lane] : 0.0f;
        #pragma unroll
        for (int o = 16; o; o >>= 1) v += __shfl_xor_sync(0xffffffffu, v, o);
        if (lane == 0) g_partial[n] = (double)v;
    }
}

__global__ __launch_bounds__(256) void finalize_kernel(float* __restrict__ out, int N)
{
    const int tid  = threadIdx.x;
    const int lane = tid & 31;
    const int wid  = tid >> 5;

    double d = 0.0;
    for (int i = tid; i < N; i += 256) d += g_partial[i];

    #pragma unroll
    for (int o = 16; o; o >>= 1) d += __shfl_xor_sync(0xffffffffu, d, o);

    __shared__ double s_dsum[8];
    if (lane == 0) s_dsum[wid] = d;
    __syncthreads();

    if (wid == 0) {
        double t = (lane < 8) ? s_dsum[lane] : 0.0;
        #pragma unroll
        for (int o = 4; o; o >>= 1) t += __shfl_xor_sync(0xffffffffu, t, o);
        if (lane == 0) out[0] = (float)(-t / (double)N);
    }
}

extern "C" void kernel_launch(void* const* d_in, const int* in_sizes, int n_in,
                              void* d_out, int out_size) {
    const float* input         = (const float*)d_in[0];
    const int*   target        = (const int*)  d_in[1];
    const int*   noise_samples = (const int*)  d_in[2];
    const float* noise         = (const float*)d_in[3];
    const float* weight        = (const float*)d_in[4];
    const float* bias          = (const float*)d_in[5];
    float* out = (float*)d_out;

    const int N = in_sizes[1];  // target element count

    nce_loss_kernel<<<N, NWARPS * 32>>>(input, target, noise_samples, noise,
                                        weight, bias);
    finalize_kernel<<<1, 256>>>(out, N);
}

// round 6
// speedup vs baseline: 1.1079x; 1.1079x over previous
#include <cuda_runtime.h>

// NCELoss: N=4096, E=1024, K=50 noise (+1 target). Output: scalar f32 loss.
//
// E-split two-pass scheme to make the weight working set fit in L2 (126 MB):
//   pass 0: dot over weight[:, 0:512]   -> g_logit[n*51+j]  (partial)
//   pass 1: dot over weight[:, 512:1024] + g_logit -> loss terms -> g_partial[n]
//   finalize: fixed-order double reduction of g_partial -> out
// Per pass the unique weight bytes are ~49.6k rows x 2KB = 99 MB < L2, so
// repeated row touches within a pass hit L2 instead of DRAM.
// Inner loop: 2 columns x 4 LDG.128 per lane = 8 loads in flight (the
// empirically best MLP on this kernel; 16/24 measured slower).

#define EDIM 1024
#define HALF 512
#define KNOISE 50
#define NCOLS (KNOISE + 1)
#define NORM_TERM 9.0f
#define NWARPS 8
#define MAXN 8192

__device__ float  g_logit[MAXN * NCOLS];
__device__ double g_partial[MAXN];

__device__ __forceinline__ float loss_term(int j, int idx, float s,
                                           const float* __restrict__ bias,
                                           const float* __restrict__ noise)
{
    const float logit = s + __ldg(&bias[idx]);
    const float p  = expf(logit - NORM_TERM);
    const float kp = (float)KNOISE * __ldg(&noise[idx]);
    const float num = (j == 0) ? p : kp;   // j==0: data term, else noise term
    return logf(num / (p + kp));
}

// Dot of a 512-float weight chunk against smem input chunk. Warp-collective.
__device__ __forceinline__ float dot512(const float* __restrict__ wchunk,
                                        const float4* __restrict__ s_in,
                                        int lane)
{
    const float4* w4 = reinterpret_cast<const float4*>(wchunk);
    float4 w[4];
    #pragma unroll
    for (int i = 0; i < 4; i++) w[i] = __ldg(&w4[lane + 32 * i]);
    float s = 0.0f;
    #pragma unroll
    for (int i = 0; i < 4; i++) {
        const float4 x = s_in[lane + 32 * i];
        s += w[i].x * x.x + w[i].y * x.y + w[i].z * x.z + w[i].w * x.w;
    }
    return s;
}

template <int PASS>
__global__ __launch_bounds__(NWARPS * 32) void nce_pass_kernel(
    const float* __restrict__ input,
    const int*   __restrict__ target,
    const int*   __restrict__ noise_samples,
    const float* __restrict__ noise,
    const float* __restrict__ weight,
    const float* __restrict__ bias)
{
    __shared__ float4 s_in[HALF / 4];          // 2 KB input half-row
    __shared__ float  s_wsum[NWARPS];

    const int n    = blockIdx.x;
    const int tid  = threadIdx.x;
    const int lane = tid & 31;
    const int wid  = tid >> 5;

    const float4* in4 = reinterpret_cast<const float4*>(
        input + (size_t)n * EDIM + PASS * HALF);
    for (int i = tid; i < HALF / 4; i += NWARPS * 32) s_in[i] = in4[i];
    __syncthreads();

    float acc = 0.0f;

    // Columns j in [0, 50]; warp wid covers j = wid, wid+8, ... processed in
    // pairs (j, j+8) so 8 LDG.128 are in flight per warp.
    for (int j = wid; j < NCOLS; j += 2 * NWARPS) {
        const int  jB   = j + NWARPS;
        const bool hasB = (jB < NCOLS);

        const int idxA = (j == 0) ? __ldg(&target[n])
                                  : __ldg(&noise_samples[n * KNOISE + (j - 1)]);
        const int idxB = hasB ? __ldg(&noise_samples[n * KNOISE + (jB - 1)]) : idxA;

        const float* wA = weight + (size_t)idxA * EDIM + PASS * HALF;
        const float* wB = weight + (size_t)idxB * EDIM + PASS * HALF;

        float sA = dot512(wA, s_in, lane);
        float sB = hasB ? dot512(wB, s_in, lane) : 0.0f;

        #pragma unroll
        for (int o = 16; o; o >>= 1) {
            sA += __shfl_xor_sync(0xffffffffu, sA, o);
            sB += __shfl_xor_sync(0xffffffffu, sB, o);
        }

        if (lane == 0) {
            if (PASS == 0) {
                g_logit[n * NCOLS + j] = sA;
                if (hasB) g_logit[n * NCOLS + jB] = sB;
            } else {
                const float tA = g_logit[n * NCOLS + j] + sA;
                acc += loss_term(j, idxA, tA, bias, noise);
                if (hasB) {
                    const float tB = g_logit[n * NCOLS + jB] + sB;
                    acc += loss_term(jB, idxB, tB, bias, noise);
                }
            }
        }
    }

    if (PASS == 1) {
        if (lane == 0) s_wsum[wid] = acc;
        __syncthreads();
        if (wid == 0) {
            float v = (lane < NWARPS) ? s_wsum[lane] : 0.0f;
            #pragma unroll
            for (int o = NWARPS / 2; o; o >>= 1)
                v += __shfl_xor_sync(0xffffffffu, v, o);
            if (lane == 0) g_partial[n] = (double)v;
        }
    }
}

__global__ __launch_bounds__(1024) void finalize_kernel(float* __restrict__ out, int N)
{
    const int tid  = threadIdx.x;
    const int lane = tid & 31;
    const int wid  = tid >> 5;

    double d = 0.0;
    for (int i = tid; i < N; i += 1024) d += g_partial[i];

    #pragma unroll
    for (int o = 16; o; o >>= 1) d += __shfl_xor_sync(0xffffffffu, d, o);

    __shared__ double s_dsum[32];
    if (lane == 0) s_dsum[wid] = d;
    __syncthreads();

    if (wid == 0) {
        double t = (lane < 32) ? s_dsum[lane] : 0.0;
        #pragma unroll
        for (int o = 16; o; o >>= 1) t += __shfl_xor_sync(0xffffffffu, t, o);
        if (lane == 0) out[0] = (float)(-t / (double)N);
    }
}

extern "C" void kernel_launch(void* const* d_in, const int* in_sizes, int n_in,
                              void* d_out, int out_size) {
    const float* input         = (const float*)d_in[0];
    const int*   target        = (const int*)  d_in[1];
    const int*   noise_samples = (const int*)  d_in[2];
    const float* noise         = (const float*)d_in[3];
    const float* weight        = (const float*)d_in[4];
    const float* bias          = (const float*)d_in[5];
    float* out = (float*)d_out;

    const int N = in_sizes[1];  // target element count

    nce_pass_kernel<0><<<N, NWARPS * 32>>>(input, target, noise_samples,
                                           noise, weight, bias);
    nce_pass_kernel<1><<<N, NWARPS * 32>>>(input, target, noise_samples,
                                           noise, weight, bias);
    finalize_kernel<<<1, 1024>>>(out, N);
}